// round 1
// baseline (speedup 1.0000x reference)
#include <cuda_runtime.h>
#include <math.h>

#define BATCH 4
#define SEQ   2048
#define EMB   128
#define HEADS 8
#define BH    (BATCH*HEADS)

// scratch (static __device__ arrays — the sanctioned allocation-free workaround)
__device__ float g_Q[(size_t)BH*SEQ*EMB];
__device__ float g_K[(size_t)BH*SEQ*EMB];
__device__ float g_V[(size_t)BH*SEQ*EMB];
__device__ float g_O[(size_t)BH*SEQ*EMB];
__device__ int   g_flag[SEQ];

// ---------------------------------------------------------------------------
// Kernel 1: QKV projection.  Y = x @ W  (M=8192, N=1024, K=128), written
// directly into [b,h,t,e] layout. Q pre-scaled by 1/sqrt(e) (== e^-0.25 twice).
// ---------------------------------------------------------------------------
__global__ __launch_bounds__(256) void qkv_kernel(
    const float* __restrict__ x, const float* __restrict__ Wq,
    const float* __restrict__ Wk, const float* __restrict__ Wv)
{
    __shared__ float Xs[64][68];
    __shared__ float Ws[64][68];
    const float* W; float* out; float scale;
    if (blockIdx.z == 0)      { W = Wq; out = g_Q; scale = 0.08838834764831843f; }
    else if (blockIdx.z == 1) { W = Wk; out = g_K; scale = 1.0f; }
    else                      { W = Wv; out = g_V; scale = 1.0f; }

    const int m0 = blockIdx.x * 64, n0 = blockIdx.y * 64;
    const int tid = threadIdx.x;
    const int tm = (tid >> 4) << 2, tn = (tid & 15) << 2;
    float acc[4][4] = {};

    for (int k0 = 0; k0 < 128; k0 += 64) {
        for (int i = tid; i < 1024; i += 256) {
            int r = i >> 4, c = (i & 15) << 2;
            *(float4*)&Xs[r][c] = *(const float4*)(x + (size_t)(m0 + r) * EMB  + k0 + c);
            *(float4*)&Ws[r][c] = *(const float4*)(W + (size_t)(k0 + r) * 1024 + n0 + c);
        }
        __syncthreads();
        #pragma unroll 8
        for (int k = 0; k < 64; k++) {
            float a0 = Xs[tm][k], a1 = Xs[tm+1][k], a2 = Xs[tm+2][k], a3 = Xs[tm+3][k];
            float4 bv = *(const float4*)&Ws[k][tn];
            acc[0][0] += a0*bv.x; acc[0][1] += a0*bv.y; acc[0][2] += a0*bv.z; acc[0][3] += a0*bv.w;
            acc[1][0] += a1*bv.x; acc[1][1] += a1*bv.y; acc[1][2] += a1*bv.z; acc[1][3] += a1*bv.w;
            acc[2][0] += a2*bv.x; acc[2][1] += a2*bv.y; acc[2][2] += a2*bv.z; acc[2][3] += a2*bv.w;
            acc[3][0] += a3*bv.x; acc[3][1] += a3*bv.y; acc[3][2] += a3*bv.z; acc[3][3] += a3*bv.w;
        }
        __syncthreads();
    }
    const int n = n0 + tn;
    const int h = n >> 7, e = n & 127;
    #pragma unroll
    for (int i = 0; i < 4; i++) {
        int m = m0 + tm + i;
        int b = m >> 11, t = m & 2047;
        float4 r = make_float4(acc[i][0]*scale, acc[i][1]*scale, acc[i][2]*scale, acc[i][3]*scale);
        *(float4*)(out + (((size_t)b*HEADS + h)*SEQ + t)*EMB + e) = r;
    }
}

// ---------------------------------------------------------------------------
// Kernel 2: per-row flag — row i is "pathological" iff mask[i, 0..i] are ALL 0.
// For such rows the reference softmax is uniform over ALL mask==0 positions
// (including future keys), because mask -1e9 overrides the causal -inf.
// ---------------------------------------------------------------------------
__global__ __launch_bounds__(256) void flag_kernel(const int* __restrict__ mask)
{
    __shared__ int any1;
    const int i = blockIdx.x;
    if (threadIdx.x == 0) any1 = 0;
    __syncthreads();
    int local = 0;
    for (int j = threadIdx.x; j <= i; j += 256)
        local |= mask[(size_t)i * SEQ + j];
    if (local) any1 = 1;
    __syncthreads();
    if (threadIdx.x == 0) g_flag[i] = (any1 == 0);
}

// ---------------------------------------------------------------------------
// Kernel 3: flash attention. One block = 64 queries of one (b,h).
// K stored transposed in smem -> conflict-free LDS in the S microkernel.
// Causal skip: only key tiles kb <= qb (pathological rows fixed up later).
// ---------------------------------------------------------------------------
#define BM    64
#define BN    64
#define QSTR  132   // Q/V row stride (floats), float4-aligned, padded
#define KTSTR 68    // transposed-K row stride
#define PSTR  68    // P row stride

#define ATTN_SMEM_BYTES ((BM*QSTR + EMB*KTSTR + BN*QSTR + BM*PSTR + 3*BM)*4 + BM*BN*4)

__global__ __launch_bounds__(256) void attn_kernel(const int* __restrict__ mask)
{
    extern __shared__ float sm[];
    float* Qs    = sm;                   // [64][132]
    float* Kts   = Qs  + BM*QSTR;        // [128][68]  (K transposed: [d][n])
    float* Vs    = Kts + EMB*KTSTR;      // [64][132]
    float* Ps    = Vs  + BN*QSTR;        // [64][68]
    float* m_arr = Ps  + BM*PSTR;        // [64] running max
    float* l_arr = m_arr + BM;           // [64] running sum
    float* a_arr = l_arr + BM;           // [64] rescale factor this tile
    int*   Ms    = (int*)(a_arr + BM);   // [64][64] mask tile

    const int qb = gridDim.x - 1 - blockIdx.x;  // heavy blocks first
    const int bh = blockIdx.y;
    const float* Qg = g_Q + ((size_t)bh*SEQ + qb*BM)*EMB;
    const float* Kg = g_K + (size_t)bh*SEQ*EMB;
    const float* Vg = g_V + (size_t)bh*SEQ*EMB;
    float*       Og = g_O + ((size_t)bh*SEQ + qb*BM)*EMB;

    const int tid = threadIdx.x;
    const int tmS = (tid >> 4) << 2;   // 4 query rows per thread
    const int tnS = (tid & 15) << 2;   // 4 key cols per thread (S microtile)
    const int tdO = (tid & 15) << 3;   // 8 d-cols per thread (O microtile)

    for (int i = tid; i < BM*32; i += 256) {
        int r = i >> 5, c = (i & 31) << 2;
        *(float4*)(Qs + r*QSTR + c) = *(const float4*)(Qg + (size_t)r*EMB + c);
    }
    if (tid < BM) { m_arr[tid] = -INFINITY; l_arr[tid] = 0.f; a_arr[tid] = 1.f; }
    float o[4][8] = {};
    __syncthreads();

    for (int kb = 0; kb <= qb; kb++) {
        // --- fill K (transposed store: gmem strided, smem conflict-free) ---
        for (int i = tid; i < 2048; i += 256) {
            int r = i & 63, c = (i >> 6) << 2;
            float4 v = *(const float4*)(Kg + (size_t)(kb*BN + r)*EMB + c);
            Kts[(c+0)*KTSTR + r] = v.x;
            Kts[(c+1)*KTSTR + r] = v.y;
            Kts[(c+2)*KTSTR + r] = v.z;
            Kts[(c+3)*KTSTR + r] = v.w;
        }
        // --- fill V (row-major, coalesced) ---
        for (int i = tid; i < 2048; i += 256) {
            int r = i >> 5, c = (i & 31) << 2;
            *(float4*)(Vs + r*QSTR + c) = *(const float4*)(Vg + (size_t)(kb*BN + r)*EMB + c);
        }
        // --- fill mask tile ---
        for (int i = tid; i < 1024; i += 256) {
            int r = i >> 4, c = (i & 15) << 2;
            *(int4*)(Ms + r*BN + c) = *(const int4*)(mask + (size_t)(qb*BM + r)*SEQ + kb*BN + c);
        }
        __syncthreads();

        // --- S = Q @ K^T (4x4 per thread) ---
        float s[4][4] = {};
        #pragma unroll 2
        for (int d = 0; d < EMB; d++) {
            float4 kv = *(const float4*)(Kts + d*KTSTR + tnS);
            float q0 = Qs[(tmS+0)*QSTR + d];
            float q1 = Qs[(tmS+1)*QSTR + d];
            float q2 = Qs[(tmS+2)*QSTR + d];
            float q3 = Qs[(tmS+3)*QSTR + d];
            s[0][0] += q0*kv.x; s[0][1] += q0*kv.y; s[0][2] += q0*kv.z; s[0][3] += q0*kv.w;
            s[1][0] += q1*kv.x; s[1][1] += q1*kv.y; s[1][2] += q1*kv.z; s[1][3] += q1*kv.w;
            s[2][0] += q2*kv.x; s[2][1] += q2*kv.y; s[2][2] += q2*kv.z; s[2][3] += q2*kv.w;
            s[3][0] += q3*kv.x; s[3][1] += q3*kv.y; s[3][2] += q3*kv.z; s[3][3] += q3*kv.w;
        }

        // --- masks: causal -inf FIRST, then mask==0 -> -1e9 (reference order) ---
        const bool diag = (kb == qb);
        #pragma unroll
        for (int i = 0; i < 4; i++) {
            int qrow = qb*BM + tmS + i;
            #pragma unroll
            for (int j = 0; j < 4; j++) {
                int kcol = kb*BN + tnS + j;
                float sv = s[i][j];
                if (diag && kcol > qrow) sv = -INFINITY;
                if (Ms[(tmS+i)*BN + tnS + j] == 0) sv = -1e9f;
                s[i][j] = sv;
            }
        }

        // --- online softmax (row group = 16 consecutive lanes) ---
        float nm[4], rs[4], al[4];
        #pragma unroll
        for (int i = 0; i < 4; i++) {
            float rm = fmaxf(fmaxf(s[i][0], s[i][1]), fmaxf(s[i][2], s[i][3]));
            rm = fmaxf(rm, __shfl_xor_sync(0xffffffffu, rm, 1));
            rm = fmaxf(rm, __shfl_xor_sync(0xffffffffu, rm, 2));
            rm = fmaxf(rm, __shfl_xor_sync(0xffffffffu, rm, 4));
            rm = fmaxf(rm, __shfl_xor_sync(0xffffffffu, rm, 8));
            float mo = m_arr[tmS + i];
            float mn = fmaxf(mo, rm);
            nm[i] = mn;
            s[i][0] = __expf(s[i][0] - mn);
            s[i][1] = __expf(s[i][1] - mn);
            s[i][2] = __expf(s[i][2] - mn);
            s[i][3] = __expf(s[i][3] - mn);
            float sum = s[i][0] + s[i][1] + s[i][2] + s[i][3];
            sum += __shfl_xor_sync(0xffffffffu, sum, 1);
            sum += __shfl_xor_sync(0xffffffffu, sum, 2);
            sum += __shfl_xor_sync(0xffffffffu, sum, 4);
            sum += __shfl_xor_sync(0xffffffffu, sum, 8);
            rs[i] = sum;
            al[i] = __expf(mo - mn);
        }
        #pragma unroll
        for (int i = 0; i < 4; i++)
            *(float4*)(Ps + (tmS+i)*PSTR + tnS) = make_float4(s[i][0], s[i][1], s[i][2], s[i][3]);
        if ((tid & 15) == 0) {
            #pragma unroll
            for (int i = 0; i < 4; i++) {
                int r = tmS + i;
                m_arr[r] = nm[i];
                l_arr[r] = l_arr[r]*al[i] + rs[i];
                a_arr[r] = al[i];
            }
        }
        __syncthreads();

        // --- O = O*alpha + P @ V (4 rows x 8 cols per thread) ---
        #pragma unroll
        for (int i = 0; i < 4; i++) {
            float a = a_arr[tmS + i];
            #pragma unroll
            for (int c = 0; c < 8; c++) o[i][c] *= a;
        }
        #pragma unroll 2
        for (int n = 0; n < BN; n++) {
            float4 v0 = *(const float4*)(Vs + n*QSTR + tdO);
            float4 v1 = *(const float4*)(Vs + n*QSTR + tdO + 4);
            float p0 = Ps[(tmS+0)*PSTR + n];
            float p1 = Ps[(tmS+1)*PSTR + n];
            float p2 = Ps[(tmS+2)*PSTR + n];
            float p3 = Ps[(tmS+3)*PSTR + n];
            o[0][0] += p0*v0.x; o[0][1] += p0*v0.y; o[0][2] += p0*v0.z; o[0][3] += p0*v0.w;
            o[0][4] += p0*v1.x; o[0][5] += p0*v1.y; o[0][6] += p0*v1.z; o[0][7] += p0*v1.w;
            o[1][0] += p1*v0.x; o[1][1] += p1*v0.y; o[1][2] += p1*v0.z; o[1][3] += p1*v0.w;
            o[1][4] += p1*v1.x; o[1][5] += p1*v1.y; o[1][6] += p1*v1.z; o[1][7] += p1*v1.w;
            o[2][0] += p2*v0.x; o[2][1] += p2*v0.y; o[2][2] += p2*v0.z; o[2][3] += p2*v0.w;
            o[2][4] += p2*v1.x; o[2][5] += p2*v1.y; o[2][6] += p2*v1.z; o[2][7] += p2*v1.w;
            o[3][0] += p3*v0.x; o[3][1] += p3*v0.y; o[3][2] += p3*v0.z; o[3][3] += p3*v0.w;
            o[3][4] += p3*v1.x; o[3][5] += p3*v1.y; o[3][6] += p3*v1.z; o[3][7] += p3*v1.w;
        }
        __syncthreads();
    }

    #pragma unroll
    for (int i = 0; i < 4; i++) {
        float inv = 1.0f / l_arr[tmS + i];
        float4 r0 = make_float4(o[i][0]*inv, o[i][1]*inv, o[i][2]*inv, o[i][3]*inv);
        float4 r1 = make_float4(o[i][4]*inv, o[i][5]*inv, o[i][6]*inv, o[i][7]*inv);
        *(float4*)(Og + (size_t)(tmS+i)*EMB + tdO)     = r0;
        *(float4*)(Og + (size_t)(tmS+i)*EMB + tdO + 4) = r1;
    }
}

// ---------------------------------------------------------------------------
// Kernel 4: pathological-row fixup. Overwrite O[bh,row,:] with the mean of
// v[j,:] over all j with mask[row,j]==0 (the exact reference semantics when
// every causal-valid key of the row is masked).
// ---------------------------------------------------------------------------
__global__ __launch_bounds__(128) void fixup_kernel(const int* __restrict__ mask)
{
    const int row = blockIdx.x;
    if (!g_flag[row]) return;
    const int bh = blockIdx.y;
    const int e = threadIdx.x;
    const float* Vg = g_V + (size_t)bh*SEQ*EMB;
    float acc = 0.f;
    int cnt = 0;
    for (int j = 0; j < SEQ; j++) {
        if (mask[(size_t)row*SEQ + j] == 0) { acc += Vg[(size_t)j*EMB + e]; cnt++; }
    }
    g_O[((size_t)bh*SEQ + row)*EMB + e] = acc / (float)cnt;
}

// ---------------------------------------------------------------------------
// Kernel 5: output projection. out = concat_h(O) @ Wu + bu  (M=8192,K=1024,N=128)
// ---------------------------------------------------------------------------
__global__ __launch_bounds__(256) void outproj_kernel(
    const float* __restrict__ Wu, const float* __restrict__ bu, float* __restrict__ out)
{
    __shared__ float Zs[64][68];
    __shared__ float Ws[64][68];
    const int m0 = blockIdx.x * 64, n0 = blockIdx.y * 64;
    const int tid = threadIdx.x;
    const int tm = (tid >> 4) << 2, tn = (tid & 15) << 2;
    float acc[4][4] = {};

    for (int kc = 0; kc < 16; kc++) {
        const int k0 = kc * 64;
        const int h = k0 >> 7, e0 = k0 & 127;
        for (int i = tid; i < 1024; i += 256) {
            int r = i >> 4, c = (i & 15) << 2;
            int m = m0 + r;
            int b = m >> 11, t = m & 2047;
            *(float4*)&Zs[r][c] = *(const float4*)(g_O + (((size_t)b*HEADS + h)*SEQ + t)*EMB + e0 + c);
            *(float4*)&Ws[r][c] = *(const float4*)(Wu + (size_t)(k0 + r)*EMB + n0 + c);
        }
        __syncthreads();
        #pragma unroll 8
        for (int k = 0; k < 64; k++) {
            float a0 = Zs[tm][k], a1 = Zs[tm+1][k], a2 = Zs[tm+2][k], a3 = Zs[tm+3][k];
            float4 bv = *(const float4*)&Ws[k][tn];
            acc[0][0] += a0*bv.x; acc[0][1] += a0*bv.y; acc[0][2] += a0*bv.z; acc[0][3] += a0*bv.w;
            acc[1][0] += a1*bv.x; acc[1][1] += a1*bv.y; acc[1][2] += a1*bv.z; acc[1][3] += a1*bv.w;
            acc[2][0] += a2*bv.x; acc[2][1] += a2*bv.y; acc[2][2] += a2*bv.z; acc[2][3] += a2*bv.w;
            acc[3][0] += a3*bv.x; acc[3][1] += a3*bv.y; acc[3][2] += a3*bv.z; acc[3][3] += a3*bv.w;
        }
        __syncthreads();
    }
    float4 bv = *(const float4*)(bu + n0 + tn);
    #pragma unroll
    for (int i = 0; i < 4; i++) {
        size_t m = m0 + tm + i;
        float4 r = make_float4(acc[i][0]+bv.x, acc[i][1]+bv.y, acc[i][2]+bv.z, acc[i][3]+bv.w);
        *(float4*)(out + m*EMB + n0 + tn) = r;
    }
}

// ---------------------------------------------------------------------------
extern "C" void kernel_launch(void* const* d_in, const int* in_sizes, int n_in,
                              void* d_out, int out_size)
{
    const float* x    = (const float*)d_in[0];
    const int*   mask = (const int*)  d_in[1];
    const float* Wq   = (const float*)d_in[2];
    const float* Wk   = (const float*)d_in[3];
    const float* Wv   = (const float*)d_in[4];
    const float* Wu   = (const float*)d_in[5];
    const float* bu   = (const float*)d_in[6];
    float* out = (float*)d_out;

    cudaFuncSetAttribute(attn_kernel, cudaFuncAttributeMaxDynamicSharedMemorySize,
                         ATTN_SMEM_BYTES);

    qkv_kernel<<<dim3(128, 16, 3), 256>>>(x, Wq, Wk, Wv);
    flag_kernel<<<SEQ, 256>>>(mask);
    attn_kernel<<<dim3(SEQ/BM, BH), 256, ATTN_SMEM_BYTES>>>(mask);
    fixup_kernel<<<dim3(SEQ, BH), 128>>>(mask);
    outproj_kernel<<<dim3(128, 2), 256>>>(Wu, bu, out);
}

// round 2
// speedup vs baseline: 2.2621x; 2.2621x over previous
#include <cuda_runtime.h>
#include <math.h>

#define BATCH 4
#define SEQ   2048
#define EMB   128
#define HEADS 8
#define BH    (BATCH*HEADS)
#define FULLMASK 0xffffffffu

// scratch (static __device__ arrays — the sanctioned allocation-free workaround)
__device__ float g_Q[(size_t)BH*SEQ*EMB];
__device__ float g_K[(size_t)BH*SEQ*EMB];
__device__ float g_V[(size_t)BH*SEQ*EMB];
__device__ float g_O[(size_t)BH*SEQ*EMB];
__device__ int   g_flag[SEQ];

// ---------------------------------------------------------------------------
// helpers: tf32 convert + m16n8k8 tf32 mma
// ---------------------------------------------------------------------------
__device__ __forceinline__ unsigned f2tf(float f) {
    unsigned u;
    asm("cvt.rna.tf32.f32 %0, %1;" : "=r"(u) : "f"(f));
    return u;
}

__device__ __forceinline__ void mma8(float* d, const unsigned* a, unsigned b0, unsigned b1) {
    asm("mma.sync.aligned.m16n8k8.row.col.f32.tf32.tf32.f32 "
        "{%0,%1,%2,%3},{%4,%5,%6,%7},{%8,%9},{%0,%1,%2,%3};"
        : "+f"(d[0]), "+f"(d[1]), "+f"(d[2]), "+f"(d[3])
        : "r"(a[0]), "r"(a[1]), "r"(a[2]), "r"(a[3]), "r"(b0), "r"(b1));
}

// ---------------------------------------------------------------------------
// Kernel 1: QKV projection.  Y = x @ W  (M=8192, N=1024, K=128), written
// directly into [b,h,t,e] layout. Q pre-scaled by 1/sqrt(e).
// ---------------------------------------------------------------------------
__global__ __launch_bounds__(256) void qkv_kernel(
    const float* __restrict__ x, const float* __restrict__ Wq,
    const float* __restrict__ Wk, const float* __restrict__ Wv)
{
    __shared__ float Xs[64][68];
    __shared__ float Ws[64][68];
    const float* W; float* out; float scale;
    if (blockIdx.z == 0)      { W = Wq; out = g_Q; scale = 0.08838834764831843f; }
    else if (blockIdx.z == 1) { W = Wk; out = g_K; scale = 1.0f; }
    else                      { W = Wv; out = g_V; scale = 1.0f; }

    const int m0 = blockIdx.x * 64, n0 = blockIdx.y * 64;
    const int tid = threadIdx.x;
    const int tm = (tid >> 4) << 2, tn = (tid & 15) << 2;
    float acc[4][4] = {};

    for (int k0 = 0; k0 < 128; k0 += 64) {
        for (int i = tid; i < 1024; i += 256) {
            int r = i >> 4, c = (i & 15) << 2;
            *(float4*)&Xs[r][c] = *(const float4*)(x + (size_t)(m0 + r) * EMB  + k0 + c);
            *(float4*)&Ws[r][c] = *(const float4*)(W + (size_t)(k0 + r) * 1024 + n0 + c);
        }
        __syncthreads();
        #pragma unroll 8
        for (int k = 0; k < 64; k++) {
            float a0 = Xs[tm][k], a1 = Xs[tm+1][k], a2 = Xs[tm+2][k], a3 = Xs[tm+3][k];
            float4 bv = *(const float4*)&Ws[k][tn];
            acc[0][0] += a0*bv.x; acc[0][1] += a0*bv.y; acc[0][2] += a0*bv.z; acc[0][3] += a0*bv.w;
            acc[1][0] += a1*bv.x; acc[1][1] += a1*bv.y; acc[1][2] += a1*bv.z; acc[1][3] += a1*bv.w;
            acc[2][0] += a2*bv.x; acc[2][1] += a2*bv.y; acc[2][2] += a2*bv.z; acc[2][3] += a2*bv.w;
            acc[3][0] += a3*bv.x; acc[3][1] += a3*bv.y; acc[3][2] += a3*bv.z; acc[3][3] += a3*bv.w;
        }
        __syncthreads();
    }
    const int n = n0 + tn;
    const int h = n >> 7, e = n & 127;
    #pragma unroll
    for (int i = 0; i < 4; i++) {
        int m = m0 + tm + i;
        int b = m >> 11, t = m & 2047;
        float4 r = make_float4(acc[i][0]*scale, acc[i][1]*scale, acc[i][2]*scale, acc[i][3]*scale);
        *(float4*)(out + (((size_t)b*HEADS + h)*SEQ + t)*EMB + e) = r;
    }
}

// ---------------------------------------------------------------------------
// Kernel 2: per-row flag — row i is "pathological" iff mask[i, 0..i] all 0.
// ---------------------------------------------------------------------------
__global__ __launch_bounds__(256) void flag_kernel(const int* __restrict__ mask)
{
    __shared__ int any1;
    const int i = blockIdx.x;
    if (threadIdx.x == 0) any1 = 0;
    __syncthreads();
    int local = 0;
    for (int j = threadIdx.x; j <= i; j += 256)
        local |= mask[(size_t)i * SEQ + j];
    if (local) any1 = 1;
    __syncthreads();
    if (threadIdx.x == 0) g_flag[i] = (any1 == 0);
}

// ---------------------------------------------------------------------------
// Kernel 3: flash attention, tf32 mma.sync tensor cores.
// Block = 128 queries of one (b,h); 8 warps, each owns a 16-row strip.
// Q lives in registers as tf32 A-fragments; K/V staged in smem as tf32 with
// fragment-conflict-free strides; P redistributed D-frag -> A-frag via
// intra-quad shuffles (no smem P, one __syncthreads per KV tile).
// ---------------------------------------------------------------------------
#define ATTN_SMEM_BYTES ((2*64*132 + 128*66) * 4)

__global__ __launch_bounds__(256) void attn_kernel(const int* __restrict__ mask)
{
    extern __shared__ unsigned sm_u[];
    unsigned* Ks = sm_u;                 // [64][132] tf32 (row = key, col = d)
    unsigned* Vs = Ks + 64*132;          // [64][132] tf32 (row = key, col = e)
    int*      Msm = (int*)(Vs + 64*132); // [128][66] mask tile

    const int qb = gridDim.x - 1 - blockIdx.x;   // heavy blocks first
    const int bh = blockIdx.y;
    const int tid = threadIdx.x;
    const int lane = tid & 31;
    const int warp = tid >> 5;
    const int g = lane >> 2, t = lane & 3;

    const float* Qg = g_Q + ((size_t)bh*SEQ + qb*128)*EMB;
    const float* Kg = g_K + (size_t)bh*SEQ*EMB;
    const float* Vg = g_V + (size_t)bh*SEQ*EMB;
    float*       Og = g_O + ((size_t)bh*SEQ + qb*128)*EMB;

    // Q A-fragments (16 k-chunks of 8), rows warp*16 + g / +8
    const int qr = warp * 16;
    unsigned qa[16][4];
    #pragma unroll
    for (int kc = 0; kc < 16; kc++) {
        qa[kc][0] = f2tf(Qg[(size_t)(qr+g  )*EMB + kc*8 + t]);
        qa[kc][1] = f2tf(Qg[(size_t)(qr+g+8)*EMB + kc*8 + t]);
        qa[kc][2] = f2tf(Qg[(size_t)(qr+g  )*EMB + kc*8 + t + 4]);
        qa[kc][3] = f2tf(Qg[(size_t)(qr+g+8)*EMB + kc*8 + t + 4]);
    }

    float o[16][4] = {};
    float m0 = -INFINITY, m8 = -INFINITY, l0 = 0.f, l8 = 0.f;
    const int row0 = qb*128 + qr + g;
    const int row8 = row0 + 8;

    const int kb_max = 2*qb + 1;
    for (int kb = 0; kb <= kb_max; kb++) {
        // ---- stage K, V (tf32), mask tile ----
        for (int i = tid; i < 2048; i += 256) {
            int r = i >> 5, c = (i & 31) << 2;
            float4 kv = *(const float4*)(Kg + (size_t)(kb*64 + r)*EMB + c);
            float4 vv = *(const float4*)(Vg + (size_t)(kb*64 + r)*EMB + c);
            *(uint4*)(Ks + r*132 + c) = make_uint4(f2tf(kv.x), f2tf(kv.y), f2tf(kv.z), f2tf(kv.w));
            *(uint4*)(Vs + r*132 + c) = make_uint4(f2tf(vv.x), f2tf(vv.y), f2tf(vv.z), f2tf(vv.w));
        }
        for (int i = tid; i < 4096; i += 256) {
            int r = i >> 5, c2 = (i & 31) << 1;
            *(int2*)(Msm + r*66 + c2) =
                *(const int2*)(mask + (size_t)(qb*128 + r)*SEQ + kb*64 + c2);
        }
        __syncthreads();

        // ---- S = Q @ K^T : 8 n-tiles x 16 k-chunks of m16n8k8 ----
        float s[8][4];
        #pragma unroll
        for (int nt = 0; nt < 8; nt++) { s[nt][0]=0.f; s[nt][1]=0.f; s[nt][2]=0.f; s[nt][3]=0.f; }
        #pragma unroll
        for (int nt = 0; nt < 8; nt++) {
            const unsigned* kr = Ks + (nt*8 + g)*132;
            #pragma unroll
            for (int kc = 0; kc < 16; kc++) {
                unsigned b0 = kr[kc*8 + t];
                unsigned b1 = kr[kc*8 + t + 4];
                mma8(s[nt], qa[kc], b0, b1);
            }
        }

        // ---- masks: causal -inf first, then mask==0 -> -1e9 (ref order) ----
        const bool diag = (kb >= 2*qb);
        #pragma unroll
        for (int nt = 0; nt < 8; nt++) {
            int c0 = kb*64 + nt*8 + 2*t;
            int2 ma = *(const int2*)&Msm[(qr+g  )*66 + nt*8 + 2*t];
            int2 mb = *(const int2*)&Msm[(qr+g+8)*66 + nt*8 + 2*t];
            if (diag) {
                if (c0     > row0) s[nt][0] = -INFINITY;
                if (c0 + 1 > row0) s[nt][1] = -INFINITY;
                if (c0     > row8) s[nt][2] = -INFINITY;
                if (c0 + 1 > row8) s[nt][3] = -INFINITY;
            }
            if (ma.x == 0) s[nt][0] = -1e9f;
            if (ma.y == 0) s[nt][1] = -1e9f;
            if (mb.x == 0) s[nt][2] = -1e9f;
            if (mb.y == 0) s[nt][3] = -1e9f;
        }

        // ---- online softmax on fragments (rows g and g+8, quad-reduce) ----
        float mx0 = -INFINITY, mx8 = -INFINITY;
        #pragma unroll
        for (int nt = 0; nt < 8; nt++) {
            mx0 = fmaxf(mx0, fmaxf(s[nt][0], s[nt][1]));
            mx8 = fmaxf(mx8, fmaxf(s[nt][2], s[nt][3]));
        }
        mx0 = fmaxf(mx0, __shfl_xor_sync(FULLMASK, mx0, 1));
        mx0 = fmaxf(mx0, __shfl_xor_sync(FULLMASK, mx0, 2));
        mx8 = fmaxf(mx8, __shfl_xor_sync(FULLMASK, mx8, 1));
        mx8 = fmaxf(mx8, __shfl_xor_sync(FULLMASK, mx8, 2));
        float mn0 = fmaxf(m0, mx0), mn8 = fmaxf(m8, mx8);
        float al0 = __expf(m0 - mn0), al8 = __expf(m8 - mn8);
        float rs0 = 0.f, rs8 = 0.f;
        #pragma unroll
        for (int nt = 0; nt < 8; nt++) {
            s[nt][0] = __expf(s[nt][0] - mn0);
            s[nt][1] = __expf(s[nt][1] - mn0);
            s[nt][2] = __expf(s[nt][2] - mn8);
            s[nt][3] = __expf(s[nt][3] - mn8);
            rs0 += s[nt][0] + s[nt][1];
            rs8 += s[nt][2] + s[nt][3];
        }
        rs0 += __shfl_xor_sync(FULLMASK, rs0, 1);
        rs0 += __shfl_xor_sync(FULLMASK, rs0, 2);
        rs8 += __shfl_xor_sync(FULLMASK, rs8, 1);
        rs8 += __shfl_xor_sync(FULLMASK, rs8, 2);
        m0 = mn0; m8 = mn8;
        l0 = l0*al0 + rs0;
        l8 = l8*al8 + rs8;
        #pragma unroll
        for (int ot = 0; ot < 16; ot++) {
            o[ot][0] *= al0; o[ot][1] *= al0;
            o[ot][2] *= al8; o[ot][3] *= al8;
        }

        // ---- O += P @ V : D-frag -> A-frag via quad shuffles, then mma ----
        const int src_lo = (lane & ~3) | (t >> 1);
        const int src_hi = src_lo + 2;
        const bool sel = t & 1;
        #pragma unroll
        for (int nt = 0; nt < 8; nt++) {
            float x0 = __shfl_sync(FULLMASK, s[nt][0], src_lo);
            float x1 = __shfl_sync(FULLMASK, s[nt][1], src_lo);
            float y0 = __shfl_sync(FULLMASK, s[nt][0], src_hi);
            float y1 = __shfl_sync(FULLMASK, s[nt][1], src_hi);
            float z0 = __shfl_sync(FULLMASK, s[nt][2], src_lo);
            float z1 = __shfl_sync(FULLMASK, s[nt][3], src_lo);
            float w0 = __shfl_sync(FULLMASK, s[nt][2], src_hi);
            float w1 = __shfl_sync(FULLMASK, s[nt][3], src_hi);
            unsigned pa[4];
            pa[0] = f2tf(sel ? x1 : x0);   // row g,   col t
            pa[1] = f2tf(sel ? z1 : z0);   // row g+8, col t
            pa[2] = f2tf(sel ? y1 : y0);   // row g,   col t+4
            pa[3] = f2tf(sel ? w1 : w0);   // row g+8, col t+4
            const unsigned* v0 = Vs + (nt*8 + t)*132;
            const unsigned* v1 = Vs + (nt*8 + t + 4)*132;
            #pragma unroll
            for (int ot = 0; ot < 16; ot++) {
                mma8(o[ot], pa, v0[ot*8 + g], v1[ot*8 + g]);
            }
        }
        __syncthreads();
    }

    // ---- epilogue: divide by l, write O ----
    float inv0 = 1.f / l0, inv8 = 1.f / l8;
    #pragma unroll
    for (int ot = 0; ot < 16; ot++) {
        *(float2*)(Og + (size_t)(qr+g  )*EMB + ot*8 + 2*t) = make_float2(o[ot][0]*inv0, o[ot][1]*inv0);
        *(float2*)(Og + (size_t)(qr+g+8)*EMB + ot*8 + 2*t) = make_float2(o[ot][2]*inv8, o[ot][3]*inv8);
    }
}

// ---------------------------------------------------------------------------
// Kernel 4: pathological-row fixup, compacted. 32 blocks (one per bh), each
// builds the flagged-row list in smem and only processes those rows.
// ---------------------------------------------------------------------------
__global__ __launch_bounds__(128) void fixup_kernel(const int* __restrict__ mask)
{
    __shared__ int rows[2048];
    __shared__ int nrows;
    if (threadIdx.x == 0) nrows = 0;
    __syncthreads();
    for (int r = threadIdx.x; r < SEQ; r += 128)
        if (g_flag[r]) { int i = atomicAdd(&nrows, 1); rows[i] = r; }
    __syncthreads();

    const int bh = blockIdx.x;
    const float* Vg = g_V + (size_t)bh*SEQ*EMB;
    const int e = threadIdx.x;
    const int n = nrows;
    for (int i = 0; i < n; i++) {
        int row = rows[i];
        float acc = 0.f; int cnt = 0;
        #pragma unroll 4
        for (int j = 0; j < SEQ; j++) {
            if (mask[(size_t)row*SEQ + j] == 0) { acc += Vg[(size_t)j*EMB + e]; cnt++; }
        }
        g_O[((size_t)bh*SEQ + row)*EMB + e] = acc / (float)cnt;
    }
}

// ---------------------------------------------------------------------------
// Kernel 5: output projection. out = concat_h(O) @ Wu + bu  (M=8192,K=1024,N=128)
// ---------------------------------------------------------------------------
__global__ __launch_bounds__(256) void outproj_kernel(
    const float* __restrict__ Wu, const float* __restrict__ bu, float* __restrict__ out)
{
    __shared__ float Zs[64][68];
    __shared__ float Ws[64][68];
    const int m0 = blockIdx.x * 64, n0 = blockIdx.y * 64;
    const int tid = threadIdx.x;
    const int tm = (tid >> 4) << 2, tn = (tid & 15) << 2;
    float acc[4][4] = {};

    for (int kc = 0; kc < 16; kc++) {
        const int k0 = kc * 64;
        const int h = k0 >> 7, e0 = k0 & 127;
        for (int i = tid; i < 1024; i += 256) {
            int r = i >> 4, c = (i & 15) << 2;
            int m = m0 + r;
            int b = m >> 11, t = m & 2047;
            *(float4*)&Zs[r][c] = *(const float4*)(g_O + (((size_t)b*HEADS + h)*SEQ + t)*EMB + e0 + c);
            *(float4*)&Ws[r][c] = *(const float4*)(Wu + (size_t)(k0 + r)*EMB + n0 + c);
        }
        __syncthreads();
        #pragma unroll 8
        for (int k = 0; k < 64; k++) {
            float a0 = Zs[tm][k], a1 = Zs[tm+1][k], a2 = Zs[tm+2][k], a3 = Zs[tm+3][k];
            float4 bv = *(const float4*)&Ws[k][tn];
            acc[0][0] += a0*bv.x; acc[0][1] += a0*bv.y; acc[0][2] += a0*bv.z; acc[0][3] += a0*bv.w;
            acc[1][0] += a1*bv.x; acc[1][1] += a1*bv.y; acc[1][2] += a1*bv.z; acc[1][3] += a1*bv.w;
            acc[2][0] += a2*bv.x; acc[2][1] += a2*bv.y; acc[2][2] += a2*bv.z; acc[2][3] += a2*bv.w;
            acc[3][0] += a3*bv.x; acc[3][1] += a3*bv.y; acc[3][2] += a3*bv.z; acc[3][3] += a3*bv.w;
        }
        __syncthreads();
    }
    float4 bv = *(const float4*)(bu + n0 + tn);
    #pragma unroll
    for (int i = 0; i < 4; i++) {
        size_t m = m0 + tm + i;
        float4 r = make_float4(acc[i][0]+bv.x, acc[i][1]+bv.y, acc[i][2]+bv.z, acc[i][3]+bv.w);
        *(float4*)(out + m*EMB + n0 + tn) = r;
    }
}

// ---------------------------------------------------------------------------
extern "C" void kernel_launch(void* const* d_in, const int* in_sizes, int n_in,
                              void* d_out, int out_size)
{
    const float* x    = (const float*)d_in[0];
    const int*   mask = (const int*)  d_in[1];
    const float* Wq   = (const float*)d_in[2];
    const float* Wk   = (const float*)d_in[3];
    const float* Wv   = (const float*)d_in[4];
    const float* Wu   = (const float*)d_in[5];
    const float* bu   = (const float*)d_in[6];
    float* out = (float*)d_out;

    cudaFuncSetAttribute(attn_kernel, cudaFuncAttributeMaxDynamicSharedMemorySize,
                         ATTN_SMEM_BYTES);

    qkv_kernel<<<dim3(128, 16, 3), 256>>>(x, Wq, Wk, Wv);
    flag_kernel<<<SEQ, 256>>>(mask);
    attn_kernel<<<dim3(16, BH), 256, ATTN_SMEM_BYTES>>>(mask);
    fixup_kernel<<<BH, 128>>>(mask);
    outproj_kernel<<<dim3(128, 2), 256>>>(Wu, bu, out);
}

// round 3
// speedup vs baseline: 3.5965x; 1.5899x over previous
#include <cuda_runtime.h>
#include <math.h>

#define BATCH 4
#define SEQ   2048
#define EMB   128
#define HEADS 8
#define BH    (BATCH*HEADS)
#define FULLMASK 0xffffffffu

// scratch (static __device__ arrays — the sanctioned allocation-free workaround)
__device__ float    g_Q[(size_t)BH*SEQ*EMB];   // tf32-rounded bit patterns
__device__ float    g_K[(size_t)BH*SEQ*EMB];   // tf32-rounded
__device__ float    g_V[(size_t)BH*SEQ*EMB];   // tf32-rounded
__device__ float    g_O[(size_t)BH*SEQ*EMB];
__device__ unsigned g_mbits[(size_t)SEQ*64];   // mask bitmask: bit j of word [row][j>>5]
__device__ int      g_flag[SEQ];

// ---------------------------------------------------------------------------
// helpers
// ---------------------------------------------------------------------------
__device__ __forceinline__ unsigned f2tf(float f) {
    unsigned u;
    asm("cvt.rna.tf32.f32 %0, %1;" : "=r"(u) : "f"(f));
    return u;
}
__device__ __forceinline__ void mma8(float* d, const unsigned* a, unsigned b0, unsigned b1) {
    asm("mma.sync.aligned.m16n8k8.row.col.f32.tf32.tf32.f32 "
        "{%0,%1,%2,%3},{%4,%5,%6,%7},{%8,%9},{%0,%1,%2,%3};"
        : "+f"(d[0]), "+f"(d[1]), "+f"(d[2]), "+f"(d[3])
        : "r"(a[0]), "r"(a[1]), "r"(a[2]), "r"(a[3]), "r"(b0), "r"(b1));
}
__device__ __forceinline__ void cp_async16(void* smem, const void* gmem) {
    unsigned s = (unsigned)__cvta_generic_to_shared(smem);
    asm volatile("cp.async.cg.shared.global [%0], [%1], 16;\n" :: "r"(s), "l"(gmem));
}

// ---------------------------------------------------------------------------
// Kernel 0: mask -> bitmask (ballot). One warp builds one 32-bit word.
// ---------------------------------------------------------------------------
__global__ __launch_bounds__(256) void mbits_kernel(const int* __restrict__ mask)
{
    int W = blockIdx.x * 8 + (threadIdx.x >> 5);
    int lane = threadIdx.x & 31;
    int row = W >> 6, word = W & 63;
    int m = mask[(size_t)row*SEQ + word*32 + lane];
    unsigned b = __ballot_sync(FULLMASK, m != 0);
    if (lane == 0) g_mbits[(size_t)row*64 + word] = b;
}

// ---------------------------------------------------------------------------
// Kernel 1: QKV projection on tensor cores. Y = x@W (M=8192,N=1024,K=128),
// written tf32-rounded into [b,h,t,e] layout. Q pre-scaled by 1/sqrt(e).
// ---------------------------------------------------------------------------
__global__ __launch_bounds__(256) void qkv_mma_kernel(
    const float* __restrict__ x, const float* __restrict__ Wq,
    const float* __restrict__ Wk, const float* __restrict__ Wv)
{
    __shared__ unsigned Wt[64*132];     // B[n][k] = W[k][n0+n], tf32
    const float* W; float* out; float scale;
    if (blockIdx.z == 0)      { W = Wq; out = g_Q; scale = 0.08838834764831843f; }
    else if (blockIdx.z == 1) { W = Wk; out = g_K; scale = 1.0f; }
    else                      { W = Wv; out = g_V; scale = 1.0f; }

    const int m0 = blockIdx.x * 128, n0 = blockIdx.y * 64;
    const int tid = threadIdx.x;
    const int lane = tid & 31, warp = tid >> 5;
    const int g = lane >> 2, t = lane & 3;

    // stage W^T (K=128 fits in one shot)
    for (int i = tid; i < 2048; i += 256) {
        int k = i >> 4, n4 = (i & 15) << 2;
        float4 wv = *(const float4*)(W + (size_t)k*1024 + n0 + n4);
        Wt[(n4+0)*132 + k] = f2tf(wv.x);
        Wt[(n4+1)*132 + k] = f2tf(wv.y);
        Wt[(n4+2)*132 + k] = f2tf(wv.z);
        Wt[(n4+3)*132 + k] = f2tf(wv.w);
    }

    // A fragments from x
    const int qr = warp * 16;
    const float* xg = x + (size_t)(m0 + qr)*EMB;
    unsigned qa[16][4];
    #pragma unroll
    for (int kc = 0; kc < 16; kc++) {
        qa[kc][0] = f2tf(xg[(size_t)(g  )*EMB + kc*8 + t]);
        qa[kc][1] = f2tf(xg[(size_t)(g+8)*EMB + kc*8 + t]);
        qa[kc][2] = f2tf(xg[(size_t)(g  )*EMB + kc*8 + t + 4]);
        qa[kc][3] = f2tf(xg[(size_t)(g+8)*EMB + kc*8 + t + 4]);
    }
    __syncthreads();

    float o[8][4] = {};
    #pragma unroll
    for (int nt = 0; nt < 8; nt++) {
        const unsigned* wr = Wt + (nt*8 + g)*132;
        #pragma unroll
        for (int kc = 0; kc < 16; kc++)
            mma8(o[nt], qa[kc], wr[kc*8 + t], wr[kc*8 + t + 4]);
    }

    // epilogue: scale, round to tf32, scatter to [b,h,t,e]
    #pragma unroll
    for (int nt = 0; nt < 8; nt++) {
        int n = n0 + nt*8 + 2*t;
        int h = n >> 7, e = n & 127;
        int mA = m0 + qr + g;
        int b = mA >> 11, ts = mA & 2047;
        float2 r0 = make_float2(__uint_as_float(f2tf(o[nt][0]*scale)),
                                __uint_as_float(f2tf(o[nt][1]*scale)));
        float2 r8 = make_float2(__uint_as_float(f2tf(o[nt][2]*scale)),
                                __uint_as_float(f2tf(o[nt][3]*scale)));
        *(float2*)(out + (((size_t)b*HEADS + h)*SEQ + ts    )*EMB + e) = r0;
        *(float2*)(out + (((size_t)b*HEADS + h)*SEQ + ts + 8)*EMB + e) = r8;
    }
}

// ---------------------------------------------------------------------------
// Kernel 2: per-row flag from bitmask — row i pathological iff mask[i,0..i]==0.
// ---------------------------------------------------------------------------
__global__ __launch_bounds__(64) void flag_kernel()
{
    __shared__ unsigned ws[2];
    const int row = blockIdx.x;
    const int t = threadIdx.x;
    const int lastw = row >> 5;
    unsigned w = 0;
    if (t <= lastw) {
        w = g_mbits[(size_t)row*64 + t];
        if (t == lastw) {
            int nb = (row & 31) + 1;
            w &= (nb == 32) ? 0xffffffffu : ((1u << nb) - 1u);
        }
    }
    unsigned r = __reduce_or_sync(FULLMASK, w);
    if ((t & 31) == 0) ws[t >> 5] = r;
    __syncthreads();
    if (t == 0) g_flag[row] = ((ws[0] | ws[1]) == 0);
}

// ---------------------------------------------------------------------------
// Kernel 3: flash attention, tf32 mma.sync + cp.async double-buffered K/V.
// Block = 128 queries of one (b,h); 8 warps. Mask via bitmask words.
// ---------------------------------------------------------------------------
#define KV_WORDS    (64*132)
#define STAGE_WORDS (2*KV_WORDS)
#define ATTN_SMEM_BYTES (2*STAGE_WORDS*4)

__global__ __launch_bounds__(256) void attn_kernel()
{
    extern __shared__ unsigned sm_u[];

    const int qb = gridDim.x - 1 - blockIdx.x;   // heavy blocks first
    const int bh = blockIdx.y;
    const int tid = threadIdx.x;
    const int lane = tid & 31, warp = tid >> 5;
    const int g = lane >> 2, t = lane & 3;

    const float* Qg = g_Q + ((size_t)bh*SEQ + qb*128)*EMB;
    const float* Kg = g_K + (size_t)bh*SEQ*EMB;
    const float* Vg = g_V + (size_t)bh*SEQ*EMB;
    float*       Og = g_O + ((size_t)bh*SEQ + qb*128)*EMB;

    const int qr = warp * 16;
    const int row0 = qb*128 + qr + g;
    const int row8 = row0 + 8;
    const unsigned* mrow0 = g_mbits + (size_t)row0*64;
    const unsigned* mrow8 = g_mbits + (size_t)row8*64;

    // Q A-fragments: g_Q already tf32-rounded -> reinterpret bits
    unsigned qa[16][4];
    #pragma unroll
    for (int kc = 0; kc < 16; kc++) {
        qa[kc][0] = __float_as_uint(Qg[(size_t)(qr+g  )*EMB + kc*8 + t]);
        qa[kc][1] = __float_as_uint(Qg[(size_t)(qr+g+8)*EMB + kc*8 + t]);
        qa[kc][2] = __float_as_uint(Qg[(size_t)(qr+g  )*EMB + kc*8 + t + 4]);
        qa[kc][3] = __float_as_uint(Qg[(size_t)(qr+g+8)*EMB + kc*8 + t + 4]);
    }

    float o[16][4] = {};
    float m0 = -INFINITY, m8 = -INFINITY, l0 = 0.f, l8 = 0.f;
    const int kb_max = 2*qb + 1;

    auto stage = [&](int kb_, int st_) {
        unsigned* Kd = sm_u + st_*STAGE_WORDS;
        unsigned* Vd = Kd + KV_WORDS;
        #pragma unroll
        for (int i = tid; i < 2048; i += 256) {
            int r = i >> 5, c = (i & 31) << 2;
            cp_async16(Kd + r*132 + c, Kg + (size_t)(kb_*64 + r)*EMB + c);
            cp_async16(Vd + r*132 + c, Vg + (size_t)(kb_*64 + r)*EMB + c);
        }
    };

    stage(0, 0);
    asm volatile("cp.async.commit_group;\n");

    for (int kb = 0; kb <= kb_max; kb++) {
        const int st = kb & 1;
        if (kb < kb_max) stage(kb+1, st^1);
        asm volatile("cp.async.commit_group;\n");
        asm volatile("cp.async.wait_group 1;\n");
        __syncthreads();

        const unsigned* Ks = sm_u + st*STAGE_WORDS;
        const unsigned* Vs = Ks + KV_WORDS;

        // ---- S = Q @ K^T ----
        float s[8][4];
        #pragma unroll
        for (int nt = 0; nt < 8; nt++) { s[nt][0]=0.f; s[nt][1]=0.f; s[nt][2]=0.f; s[nt][3]=0.f; }
        #pragma unroll
        for (int nt = 0; nt < 8; nt++) {
            const unsigned* kr = Ks + (nt*8 + g)*132;
            #pragma unroll
            for (int kc = 0; kc < 16; kc++)
                mma8(s[nt], qa[kc], kr[kc*8 + t], kr[kc*8 + t + 4]);
        }

        // ---- masks: causal -inf first, then mask==0 -> -1e9 (ref order) ----
        uint2 w0 = *(const uint2*)(mrow0 + kb*2);
        uint2 w8 = *(const uint2*)(mrow8 + kb*2);
        unsigned long long M0 = (unsigned long long)w0.x | ((unsigned long long)w0.y << 32);
        unsigned long long M8 = (unsigned long long)w8.x | ((unsigned long long)w8.y << 32);
        const bool diag = (kb >= 2*qb);
        #pragma unroll
        for (int nt = 0; nt < 8; nt++) {
            int c = nt*8 + 2*t;
            int c0 = kb*64 + c;
            if (diag) {
                if (c0     > row0) s[nt][0] = -INFINITY;
                if (c0 + 1 > row0) s[nt][1] = -INFINITY;
                if (c0     > row8) s[nt][2] = -INFINITY;
                if (c0 + 1 > row8) s[nt][3] = -INFINITY;
            }
            if (!((M0 >> c)     & 1ull)) s[nt][0] = -1e9f;
            if (!((M0 >> (c+1)) & 1ull)) s[nt][1] = -1e9f;
            if (!((M8 >> c)     & 1ull)) s[nt][2] = -1e9f;
            if (!((M8 >> (c+1)) & 1ull)) s[nt][3] = -1e9f;
        }

        // ---- online softmax (quad-reduce for rows g, g+8) ----
        float mx0 = -INFINITY, mx8 = -INFINITY;
        #pragma unroll
        for (int nt = 0; nt < 8; nt++) {
            mx0 = fmaxf(mx0, fmaxf(s[nt][0], s[nt][1]));
            mx8 = fmaxf(mx8, fmaxf(s[nt][2], s[nt][3]));
        }
        mx0 = fmaxf(mx0, __shfl_xor_sync(FULLMASK, mx0, 1));
        mx0 = fmaxf(mx0, __shfl_xor_sync(FULLMASK, mx0, 2));
        mx8 = fmaxf(mx8, __shfl_xor_sync(FULLMASK, mx8, 1));
        mx8 = fmaxf(mx8, __shfl_xor_sync(FULLMASK, mx8, 2));
        float mn0 = fmaxf(m0, mx0), mn8 = fmaxf(m8, mx8);
        float al0 = __expf(m0 - mn0), al8 = __expf(m8 - mn8);
        float rs0 = 0.f, rs8 = 0.f;
        #pragma unroll
        for (int nt = 0; nt < 8; nt++) {
            s[nt][0] = __expf(s[nt][0] - mn0);
            s[nt][1] = __expf(s[nt][1] - mn0);
            s[nt][2] = __expf(s[nt][2] - mn8);
            s[nt][3] = __expf(s[nt][3] - mn8);
            rs0 += s[nt][0] + s[nt][1];
            rs8 += s[nt][2] + s[nt][3];
        }
        rs0 += __shfl_xor_sync(FULLMASK, rs0, 1);
        rs0 += __shfl_xor_sync(FULLMASK, rs0, 2);
        rs8 += __shfl_xor_sync(FULLMASK, rs8, 1);
        rs8 += __shfl_xor_sync(FULLMASK, rs8, 2);
        m0 = mn0; m8 = mn8;
        l0 = l0*al0 + rs0;
        l8 = l8*al8 + rs8;
        #pragma unroll
        for (int ot = 0; ot < 16; ot++) {
            o[ot][0] *= al0; o[ot][1] *= al0;
            o[ot][2] *= al8; o[ot][3] *= al8;
        }

        // ---- O += P @ V : D-frag -> A-frag via quad shuffles ----
        const int src_lo = (lane & ~3) | (t >> 1);
        const int src_hi = src_lo + 2;
        const bool sel = t & 1;
        #pragma unroll
        for (int nt = 0; nt < 8; nt++) {
            float x0 = __shfl_sync(FULLMASK, s[nt][0], src_lo);
            float x1 = __shfl_sync(FULLMASK, s[nt][1], src_lo);
            float y0 = __shfl_sync(FULLMASK, s[nt][0], src_hi);
            float y1 = __shfl_sync(FULLMASK, s[nt][1], src_hi);
            float z0 = __shfl_sync(FULLMASK, s[nt][2], src_lo);
            float z1 = __shfl_sync(FULLMASK, s[nt][3], src_lo);
            float w0f = __shfl_sync(FULLMASK, s[nt][2], src_hi);
            float w1f = __shfl_sync(FULLMASK, s[nt][3], src_hi);
            unsigned pa[4];
            pa[0] = f2tf(sel ? x1 : x0);
            pa[1] = f2tf(sel ? z1 : z0);
            pa[2] = f2tf(sel ? y1 : y0);
            pa[3] = f2tf(sel ? w1f : w0f);
            const unsigned* v0 = Vs + (nt*8 + t)*132;
            const unsigned* v1 = Vs + (nt*8 + t + 4)*132;
            #pragma unroll
            for (int ot = 0; ot < 16; ot++)
                mma8(o[ot], pa, v0[ot*8 + g], v1[ot*8 + g]);
        }
        __syncthreads();
    }

    float inv0 = 1.f / l0, inv8 = 1.f / l8;
    #pragma unroll
    for (int ot = 0; ot < 16; ot++) {
        *(float2*)(Og + (size_t)(qr+g  )*EMB + ot*8 + 2*t) = make_float2(o[ot][0]*inv0, o[ot][1]*inv0);
        *(float2*)(Og + (size_t)(qr+g+8)*EMB + ot*8 + 2*t) = make_float2(o[ot][2]*inv8, o[ot][3]*inv8);
    }
}

// ---------------------------------------------------------------------------
// Kernel 4: pathological-row fixup. 512 threads = 4 j-groups x 128 e.
// Overwrite O[bh,row,:] = mean(V[j,:] : mask[row,j]==0) via bitmask.
// ---------------------------------------------------------------------------
__global__ __launch_bounds__(512) void fixup_kernel()
{
    __shared__ int rows[2048];
    __shared__ int nrows_s;
    __shared__ float sacc[4][128];
    __shared__ int scnt[4];
    if (threadIdx.x == 0) nrows_s = 0;
    __syncthreads();
    for (int r = threadIdx.x; r < SEQ; r += 512)
        if (g_flag[r]) { int i = atomicAdd(&nrows_s, 1); rows[i] = r; }
    __syncthreads();
    const int n = nrows_s;
    const int bh = blockIdx.x;
    const float* Vg = g_V + (size_t)bh*SEQ*EMB;
    const int jg = threadIdx.x >> 7, e = threadIdx.x & 127;

    for (int i = 0; i < n; i++) {
        int row = rows[i];
        const unsigned* mb = g_mbits + (size_t)row*64;
        float acc = 0.f; int cnt = 0;
        for (int wi = jg*16; wi < jg*16 + 16; wi++) {
            unsigned w = mb[wi];
            int j0 = wi << 5;
            #pragma unroll
            for (int b = 0; b < 32; b++) {
                if (!((w >> b) & 1u)) { acc += Vg[(size_t)(j0 + b)*EMB + e]; cnt++; }
            }
        }
        sacc[jg][e] = acc;
        if (e == 0) scnt[jg] = cnt;
        __syncthreads();
        if (jg == 0) {
            float tot = sacc[0][e] + sacc[1][e] + sacc[2][e] + sacc[3][e];
            int c = scnt[0] + scnt[1] + scnt[2] + scnt[3];
            g_O[((size_t)bh*SEQ + row)*EMB + e] = tot / (float)c;
        }
        __syncthreads();
    }
}

// ---------------------------------------------------------------------------
// Kernel 5: output projection on tensor cores. out = concat_h(O)@Wu + bu
// (M=8192, K=1024, N=128)
// ---------------------------------------------------------------------------
__global__ __launch_bounds__(256) void outproj_mma_kernel(
    const float* __restrict__ Wu, const float* __restrict__ bu, float* __restrict__ out)
{
    __shared__ unsigned Wt[64*132];
    const int m0 = blockIdx.x * 128, n0 = blockIdx.y * 64;
    const int tid = threadIdx.x;
    const int lane = tid & 31, warp = tid >> 5;
    const int g = lane >> 2, t = lane & 3;
    const int qr = warp * 16;
    const int mA = m0 + qr + g;
    const int b = mA >> 11, ts = mA & 2047;

    float o[8][4] = {};
    for (int h = 0; h < 8; h++) {
        __syncthreads();
        for (int i = tid; i < 2048; i += 256) {
            int k = i >> 4, n4 = (i & 15) << 2;
            float4 wv = *(const float4*)(Wu + (size_t)(h*128 + k)*EMB + n0 + n4);
            Wt[(n4+0)*132 + k] = f2tf(wv.x);
            Wt[(n4+1)*132 + k] = f2tf(wv.y);
            Wt[(n4+2)*132 + k] = f2tf(wv.z);
            Wt[(n4+3)*132 + k] = f2tf(wv.w);
        }
        __syncthreads();
        const float* Og0 = g_O + (((size_t)b*HEADS + h)*SEQ + ts    )*EMB;
        const float* Og8 = g_O + (((size_t)b*HEADS + h)*SEQ + ts + 8)*EMB;
        #pragma unroll
        for (int kc = 0; kc < 16; kc++) {
            unsigned a[4];
            a[0] = f2tf(Og0[kc*8 + t]);
            a[1] = f2tf(Og8[kc*8 + t]);
            a[2] = f2tf(Og0[kc*8 + t + 4]);
            a[3] = f2tf(Og8[kc*8 + t + 4]);
            #pragma unroll
            for (int nt = 0; nt < 8; nt++) {
                const unsigned* wr = Wt + (nt*8 + g)*132;
                mma8(o[nt], a, wr[kc*8 + t], wr[kc*8 + t + 4]);
            }
        }
    }
    #pragma unroll
    for (int nt = 0; nt < 8; nt++) {
        int nn = n0 + nt*8 + 2*t;
        float2 bv = *(const float2*)(bu + nn);
        *(float2*)(out + (size_t)(m0+qr+g  )*EMB + nn) = make_float2(o[nt][0]+bv.x, o[nt][1]+bv.y);
        *(float2*)(out + (size_t)(m0+qr+g+8)*EMB + nn) = make_float2(o[nt][2]+bv.x, o[nt][3]+bv.y);
    }
}

// ---------------------------------------------------------------------------
extern "C" void kernel_launch(void* const* d_in, const int* in_sizes, int n_in,
                              void* d_out, int out_size)
{
    const float* x    = (const float*)d_in[0];
    const int*   mask = (const int*)  d_in[1];
    const float* Wq   = (const float*)d_in[2];
    const float* Wk   = (const float*)d_in[3];
    const float* Wv   = (const float*)d_in[4];
    const float* Wu   = (const float*)d_in[5];
    const float* bu   = (const float*)d_in[6];
    float* out = (float*)d_out;

    cudaFuncSetAttribute(attn_kernel, cudaFuncAttributeMaxDynamicSharedMemorySize,
                         ATTN_SMEM_BYTES);

    mbits_kernel<<<SEQ*64/8, 256>>>(mask);
    qkv_mma_kernel<<<dim3(64, 16, 3), 256>>>(x, Wq, Wk, Wv);
    flag_kernel<<<SEQ, 64>>>();
    attn_kernel<<<dim3(16, BH), 256, ATTN_SMEM_BYTES>>>();
    fixup_kernel<<<BH, 512>>>();
    outproj_mma_kernel<<<dim3(64, 2), 256>>>(Wu, bu, out);
}